// round 16
// baseline (speedup 1.0000x reference)
#include <cuda_runtime.h>
#include <math.h>
#include <stdint.h>

#define B_   32
#define T_   512
#define E_   256
#define H_   512
#define L_   50
#define NT   512
#define NLSTM 128    // recurrence blocks
#define NPROD 24     // zx producer blocks (spare SMs; GB300 has 152)
#define GPB  32      // blocks per batch-group (4 groups of 8 batches)

typedef unsigned long long ull;

// ---------------- device globals -----------------------------------------------
__device__ __align__(16) float g_hT[4 * 2 * H_ * 8];    // [grp][buf][hd][8b]
__device__ __align__(16) float g_Y[T_ * H_ * B_];       // [t][hd][32b] (zero-init .bss)
__device__ __align__(16) float g_Zx[(size_t)T_ * 2048 * B_]; // [t][col][32b]
__device__ float g_acc[B_];
__device__ unsigned g_barc[4 * 32];                     // group counters, 128B apart
__device__ unsigned g_done[T_];                         // zx tiles completed per t (4 = ready)
__device__ unsigned g_tile;                             // zx tile work-stealing counter

// ---------------- helpers --------------------------------------------------------
__device__ __forceinline__ ull ffma2_(ull a, ull b, ull c) {
    ull d;
    asm("fma.rn.f32x2 %0, %1, %2, %3;" : "=l"(d) : "l"(a), "l"(b), "l"(c));
    return d;
}
__device__ __forceinline__ ull splat2_(float x) {
    ull r; unsigned xi = __float_as_uint(x);
    asm("mov.b64 %0, {%1, %1};" : "=l"(r) : "r"(xi));
    return r;
}
__device__ __forceinline__ void cp16(uint32_t dst, const void* src) {
    asm volatile("cp.async.cg.shared.global [%0], [%1], 16;" :: "r"(dst), "l"(src));
}
__device__ __forceinline__ void cp_commit() { asm volatile("cp.async.commit_group;"); }
#define CP_WAIT(N) asm volatile("cp.async.wait_group %0;" :: "n"(N) : "memory")
#define PBAR() asm volatile("bar.sync 1, 256;" ::: "memory")

__device__ __forceinline__ float fsig_(float x) {
    x = fminf(fmaxf(x, -30.f), 30.f);
    float e = __expf(-x);
    return __fdividef(1.f, 1.f + e);
}
__device__ __forceinline__ float ftanh_(float x) {
    x = fminf(fmaxf(x, -15.f), 15.f);
    float e = __expf(-2.f * x);
    return __fdividef(1.f - e, 1.f + e);
}

// ================================================================================
// init: graph-replay-safe reset of all cross-kernel state
// ================================================================================
__global__ void init_kernel() {
    int i = blockIdx.x * blockDim.x + threadIdx.x;
    if (i < 128) g_barc[i] = 0u;
    if (i < 32)  g_acc[i] = 0.f;
    if (i < T_)  g_done[i] = 0u;
    if (i == 0)  g_tile = 0u;
    for (int j = i; j < 4 * 2 * H_ * 8; j += blockDim.x * gridDim.x) g_hT[j] = 0.f;
}

// ================================================================================
// Fused kernel. blocks 0..127: recurrence (round-14 layout).
// blocks 128..151: zx producers (dynamic tile stealing, 256 working threads).
// ================================================================================
// --- lstm smem layout (floats) ---
#define WD_FLT   0                        // [512 k][64 c] = 32768
#define ZXS_FLT  32768                    // [64 c][8 b] = 512 (single buffer)
#define ZR_FLT   (ZXS_FLT + 512)          // 33280 : [16 ws][64 c][8 b] = 8192
#define LEN_FLT  (ZR_FLT + 8192)          // 41472 : [8] ints
#define ZF_FLT   (LEN_FLT + 8)            // 41480 : [64 c][8 b] = 512
#define SMEM_TOTAL ((ZF_FLT + 512) * 4)   // 167968 B
// --- producer smem layout (floats, within same allocation) ---
#define PXD_FLT  0                        // XD [256 k][32 b] = 8192
#define PWB_FLT  8192                     // WB 3 x [16 k][512 c] = 24576 (XT overlays)
#define PMISC    32768                    // qrow[32] ints, smax, tile
#define XT_PAD   261

__global__ void __launch_bounds__(NT, 1)
fused_kernel(const int* __restrict__ q, const float* __restrict__ we,
             const float* __restrict__ W, const float* __restrict__ bvec,
             const int* __restrict__ lengths)
{
    extern __shared__ float sm[];
    const uint32_t smu = (uint32_t)__cvta_generic_to_shared(sm);
    const int tid = threadIdx.x;
    const int bid = blockIdx.x;

    if (bid >= NLSTM) {
        // ===================== zx producer =====================
        if (tid >= 256) return;
        float* XD = sm + PXD_FLT;
        float* WB = sm + PWB_FLT;
        float* XT = sm + PWB_FLT;          // transpose scratch (dead before WB use)
        int*   qrow = (int*)(sm + PMISC);
        int*   misc = (int*)(sm + PMISC + 32);

        if (tid < 32) {
            int v = lengths[tid];
            #pragma unroll
            for (int o = 16; o > 0; o >>= 1) v = max(v, __shfl_xor_sync(0xffffffffu, v, o));
            if (tid == 0) misc[0] = v;
        }
        PBAR();
        const int smax = misc[0];
        const int bq = tid & 3;
        const int cq = tid >> 2;

        for (;;) {
            if (tid == 0) misc[1] = (int)atomicAdd(&g_tile, 1u);
            PBAR();
            int tile = misc[1];
            if (tile >= T_ * 4) break;
            int t  = tile >> 2;
            int c0 = (tile & 3) << 9;
            if (t >= smax) continue;       // never consumed

            if (tid < 32) qrow[tid] = q[(tid << 9) + t];
            PBAR();
            #pragma unroll
            for (int i = 0; i < 32; ++i) {
                int idx = tid + (i << 8);
                int b = idx >> 8, k = idx & 255;
                XT[b * XT_PAD + k] = we[(((size_t)qrow[b]) << 8) + k];
            }
            PBAR();
            float xbuf[32];
            #pragma unroll
            for (int i = 0; i < 32; ++i) {
                int idx = tid + (i << 8);
                int k = idx >> 5, b = idx & 31;
                xbuf[i] = XT[b * XT_PAD + k];
            }
            PBAR();
            #pragma unroll
            for (int i = 0; i < 32; ++i) {
                int idx = tid + (i << 8);
                int k = idx >> 5, b = idx & 31;
                XD[k * 32 + b] = xbuf[i];
            }
            PBAR();

            #pragma unroll
            for (int pc = 0; pc < 2; ++pc) {
                #pragma unroll
                for (int i = 0; i < 8; ++i) {
                    int u = tid + (i << 8);
                    int kk = u >> 7, c16 = u & 127;
                    cp16(smu + (uint32_t)((PWB_FLT + pc * 8192 + kk * 512 + (c16 << 2)) * 4),
                         W + ((size_t)(pc * 16 + kk)) * 2048 + c0 + (c16 << 2));
                }
                cp_commit();
            }

            ull acc[4][8];
            #pragma unroll
            for (int i = 0; i < 4; ++i)
                #pragma unroll
                for (int j = 0; j < 8; ++j) acc[i][j] = 0ull;

            for (int kc = 0; kc < 16; ++kc) {
                if (kc < 15) { CP_WAIT(1); } else { CP_WAIT(0); }
                PBAR();
                const float* Wc = WB + (kc % 3) * 8192;
                const float* Xc = XD + kc * 16 * 32;
                #pragma unroll
                for (int kk = 0; kk < 16; ++kk) {
                    ulonglong2 xa = *(const ulonglong2*)(Xc + kk * 32 + bq * 8);
                    ulonglong2 xb = *(const ulonglong2*)(Xc + kk * 32 + bq * 8 + 4);
                    float4 w0 = *(const float4*)(Wc + kk * 512 + cq * 8);
                    float4 w1 = *(const float4*)(Wc + kk * 512 + cq * 8 + 4);
                    ull ws[8];
                    ws[0] = splat2_(w0.x); ws[1] = splat2_(w0.y);
                    ws[2] = splat2_(w0.z); ws[3] = splat2_(w0.w);
                    ws[4] = splat2_(w1.x); ws[5] = splat2_(w1.y);
                    ws[6] = splat2_(w1.z); ws[7] = splat2_(w1.w);
                    #pragma unroll
                    for (int c = 0; c < 8; ++c) {
                        acc[0][c] = ffma2_(xa.x, ws[c], acc[0][c]);
                        acc[1][c] = ffma2_(xa.y, ws[c], acc[1][c]);
                        acc[2][c] = ffma2_(xb.x, ws[c], acc[2][c]);
                        acc[3][c] = ffma2_(xb.y, ws[c], acc[3][c]);
                    }
                }
                if (kc + 2 < 16) {
                    int buf = (kc + 2) % 3;
                    #pragma unroll
                    for (int i = 0; i < 8; ++i) {
                        int u = tid + (i << 8);
                        int kk = u >> 7, c16 = u & 127;
                        cp16(smu + (uint32_t)((PWB_FLT + buf * 8192 + kk * 512 + (c16 << 2)) * 4),
                             W + ((size_t)((kc + 2) * 16 + kk)) * 2048 + c0 + (c16 << 2));
                    }
                    cp_commit();
                }
            }

            #pragma unroll
            for (int c = 0; c < 8; ++c) {
                int cg = c0 + cq * 8 + c;
                float bb = __ldg(&bvec[cg]);
                float* outp = g_Zx + ((size_t)t * 2048 + cg) * 32 + bq * 8;
                #pragma unroll
                for (int bp = 0; bp < 4; ++bp) {
                    union { ull u; float2 f; } v; v.u = acc[bp][c];
                    v.f.x += bb; v.f.y += bb;
                    *(float2*)(outp + bp * 2) = v.f;
                }
            }
            PBAR();                        // all STG done (CTA-visible to tid0)
            if (tid == 0) {
                asm volatile("red.release.gpu.global.add.u32 [%0], %1;"
                             :: "l"(&g_done[t]), "r"(1u) : "memory");
            }
        }
        return;
    }

    // ===================== recurrence (round-14 body) =====================
    float* Wsm  = sm + WD_FLT;
    float* zxs  = sm + ZXS_FLT;
    float* zred = sm + ZR_FLT;
    int*   ls   = (int*)(sm + LEN_FLT);
    float* zfin = sm + ZF_FLT;

    const int grp = bid >> 5;              // 4 groups
    const int gb  = bid & 31;
    const int hd0 = gb << 4;               // 16 h-dims per block

    for (int i = tid; i < 512 * 64; i += NT) {
        int k = i >> 6, c = i & 63;        // c = gate*16 + jj
        Wsm[i] = W[((size_t)(256 + k)) * 2048 + (((c >> 4) << 9) + hd0 + (c & 15))];
    }
    if (tid < 8) ls[tid] = lengths[(grp << 3) + tid];
    __syncthreads();

    int tmax = ls[0];
    #pragma unroll
    for (int i = 1; i < 8; ++i) tmax = max(tmax, ls[i]);

    unsigned* barp = &g_barc[grp << 5];

    // wait zx(0) ready, then prefetch
    if (tid == 0) {
        unsigned v;
        do {
            asm volatile("ld.acquire.gpu.global.u32 %0, [%1];"
                         : "=r"(v) : "l"(&g_done[0]) : "memory");
        } while (v < 4u);
    }
    __syncthreads();
    if (tid < 128) {
        int r = tid >> 1, p = tid & 1;
        int gcol = ((r >> 4) << 9) + hd0 + (r & 15);
        cp16(smu + (uint32_t)((ZXS_FLT + (r << 3) + (p << 2)) * 4),
             g_Zx + (size_t)gcol * 32 + (grp << 3) + (p << 2));
    }
    cp_commit();

    const int wid  = tid >> 5, lane = tid & 31;
    const int bg   = lane & 1;
    const int cw   = lane >> 1;
    const int krow0 = wid << 5;

    const int gbb = tid & 7, gjj = (tid >> 3) & 15;
    const int mylen = ls[gbb];
    float c_st = 0.f, h_st = 0.f;
    const int rc = tid >> 3, rb = tid & 7;

    for (int t = 0; t < tmax; ++t) {
        // ---- h-GEMM: 32 k-rows per warp, h LDG-direct from L2 (.cg) ----
        const float* hp = g_hT + (grp << 13) + ((t & 1) << 12)
                          + (krow0 << 3) + (bg << 2);
        const float* Wc = Wsm + (krow0 << 6) + (cw << 2);
        ull a0 = 0ull, a1 = 0ull, a2 = 0ull, a3 = 0ull;
        ull a4 = 0ull, a5 = 0ull, a6 = 0ull, a7 = 0ull;
        #pragma unroll 8
        for (int kk = 0; kk < 32; ++kk) {
            ull hx, hy;
            asm("ld.global.cg.v2.u64 {%0, %1}, [%2];"
                : "=l"(hx), "=l"(hy) : "l"(hp + (kk << 3)));
            float4 w = *(const float4*)(Wc + (kk << 6));
            ull w0 = splat2_(w.x), w1 = splat2_(w.y);
            ull w2 = splat2_(w.z), w3 = splat2_(w.w);
            a0 = ffma2_(hx, w0, a0);
            a1 = ffma2_(hy, w0, a1);
            a2 = ffma2_(hx, w1, a2);
            a3 = ffma2_(hy, w1, a3);
            a4 = ffma2_(hx, w2, a4);
            a5 = ffma2_(hy, w2, a5);
            a6 = ffma2_(hx, w3, a6);
            a7 = ffma2_(hy, w3, a7);
        }
        {
            ull* zru = (ull*)zred;
            int cb = (wid << 6) + (cw << 2);
            zru[((cb    ) << 2) + (bg << 1)]     = a0;
            zru[((cb    ) << 2) + (bg << 1) + 1] = a1;
            zru[((cb + 1) << 2) + (bg << 1)]     = a2;
            zru[((cb + 1) << 2) + (bg << 1) + 1] = a3;
            zru[((cb + 2) << 2) + (bg << 1)]     = a4;
            zru[((cb + 2) << 2) + (bg << 1) + 1] = a5;
            zru[((cb + 3) << 2) + (bg << 1)]     = a6;
            zru[((cb + 3) << 2) + (bg << 1) + 1] = a7;
        }
        CP_WAIT(0);                        // zx(t) staged
        __syncthreads();

        // ---- phase 1: 512-thread z reduction (incl. zx) ----
        {
            float s0 = zxs[(rc << 3) + rb], s1 = 0.f;
            #pragma unroll
            for (int ks = 0; ks < 16; ks += 2) {
                s0 += zred[(((ks << 6) + rc) << 3) + rb];
                s1 += zred[((((ks + 1) << 6) + rc) << 3) + rb];
            }
            zfin[(rc << 3) + rb] = s0 + s1;
        }
        __syncthreads();

        // ---- phase 2: gates + state update (128 threads; state in regs) ----
        if (tid < 128) {
            float gt[4];
            #pragma unroll
            for (int gate = 0; gate < 4; ++gate)
                gt[gate] = zfin[(((gate << 4) + gjj) << 3) + gbb];
            float i_ = fsig_(gt[0]);
            float jt = ftanh_(gt[1]);
            float f_ = fsig_(gt[2] + 1.f);
            float o_ = fsig_(gt[3]);
            float cnew = c_st * f_ + i_ * jt;
            float hnew = ftanh_(cnew) * o_;
            bool m = t < mylen;
            c_st = m ? cnew : c_st;
            float hout = m ? hnew : h_st;
            h_st = hout;
            int hd = hd0 + gjj;
            g_hT[(grp << 13) + (((t + 1) & 1) << 12) + (hd << 3) + gbb] = hout;
            g_Y[((size_t)(t << 9) + hd) * 32 + (grp << 3) + gbb] = m ? hnew : 0.f;
        }
        __syncthreads();

        // ---- group barrier + zx(t+1) readiness (single poller) ----
        if (tid == 0) {
            asm volatile("red.release.gpu.global.add.u32 [%0], %1;"
                         :: "l"(barp), "r"(1u) : "memory");
            if (t + 1 < tmax) {            // usually pre-satisfied
                unsigned v;
                do {
                    asm volatile("ld.acquire.gpu.global.u32 %0, [%1];"
                                 : "=r"(v) : "l"(&g_done[t + 1]) : "memory");
                } while (v < 4u);
            }
            unsigned target = (unsigned)(t + 1) * GPB;
            unsigned v2;
            do {
                asm volatile("ld.acquire.gpu.global.u32 %0, [%1];"
                             : "=r"(v2) : "l"(barp) : "memory");
            } while (v2 < target);
        }
        __syncthreads();

        // ---- prefetch zx(t+1) ----
        if (t + 1 < tmax && tid < 128) {
            int r = tid >> 1, p = tid & 1;
            int gcol = ((r >> 4) << 9) + hd0 + (r & 15);
            cp16(smu + (uint32_t)((ZXS_FLT + (r << 3) + (p << 2)) * 4),
                 g_Zx + ((size_t)((t + 1) << 11) + gcol) * 32 + (grp << 3) + (p << 2));
        }
        cp_commit();                       // keep FIFO aligned
    }
}

// ================================================================================
// Loss: projection + masked xent, one block per t (register-blocked FFMA2)
// ================================================================================
#define LS_YS   0
#define LS_PW   16384
#define LS_LG   (16384 + 25600)
#define LOSS_SMEM ((LS_LG + 1600) * 4)

__global__ void __launch_bounds__(256, 1)
loss_kernel(const int* __restrict__ a, const int* __restrict__ lengths,
            const float* __restrict__ pW, const float* __restrict__ pb)
{
    extern __shared__ float lsm[];
    float* ys  = lsm + LS_YS;
    float* pWs = lsm + LS_PW;
    float* lg  = lsm + LS_LG;
    const int t = blockIdx.x;
    const int tid = threadIdx.x;

    {
        const float4* src = (const float4*)(g_Y + (size_t)t * (H_ * B_));
        float4* dst = (float4*)ys;
        #pragma unroll
        for (int i = 0; i < 16; ++i) dst[tid + i * 256] = src[tid + i * 256];
        const float4* ps = (const float4*)pW;
        float4* pd = (float4*)pWs;
        #pragma unroll
        for (int i = 0; i < 25; ++i) pd[tid + i * 256] = ps[tid + i * 256];
    }
    __syncthreads();

    {
        const int bq = tid & 3;
        const int l  = tid >> 2;
        if (l < 50) {
            ull ac0 = 0ull, ac1 = 0ull, ac2 = 0ull, ac3 = 0ull;
            #pragma unroll 4
            for (int h = 0; h < 512; ++h) {
                const ull* yp = (const ull*)(ys + (h << 5) + (bq << 3));
                ull wv = splat2_(pWs[h * 50 + l]);
                ac0 = ffma2_(yp[0], wv, ac0);
                ac1 = ffma2_(yp[1], wv, ac1);
                ac2 = ffma2_(yp[2], wv, ac2);
                ac3 = ffma2_(yp[3], wv, ac3);
            }
            float bb = __ldg(&pb[l]);
            union { ull u; float2 f; } v;
            ull accs[4] = {ac0, ac1, ac2, ac3};
            #pragma unroll
            for (int j = 0; j < 4; ++j) {
                v.u = accs[j];
                lg[l * 32 + (bq << 3) + 2 * j]     = fmaxf(v.f.x + bb, 0.f);
                lg[l * 32 + (bq << 3) + 2 * j + 1] = fmaxf(v.f.y + bb, 0.f);
            }
        }
    }
    __syncthreads();

    if (tid < 32) {
        int b = tid;
        if (t < __ldg(&lengths[b])) {
            float mx = lg[b];
            #pragma unroll
            for (int l = 1; l < 50; ++l) mx = fmaxf(mx, lg[l * 32 + b]);
            float se = 0.f;
            #pragma unroll
            for (int l = 0; l < 50; ++l) se += expf(lg[l * 32 + b] - mx);
            float lse = logf(se) + mx;
            int lab = __ldg(&a[(b << 9) + t]);
            atomicAdd(&g_acc[b], lse - lg[lab * 32 + b]);
        }
    }
}

__global__ void final_kernel(const int* __restrict__ lengths, float* __restrict__ out) {
    if (threadIdx.x == 0) {
        float s = 0.f;
        for (int b = 0; b < B_; ++b) s += g_acc[b] / (float)lengths[b];
        out[0] = s * (1.f / (float)B_);
    }
}

// ---------------- launch ----------------------------------------------------------
extern "C" void kernel_launch(void* const* d_in, const int* in_sizes, int n_in,
                              void* d_out, int out_size) {
    const int*   q       = (const int*)d_in[0];
    const int*   a       = (const int*)d_in[1];
    const int*   lengths = (const int*)d_in[2];
    const float* we      = (const float*)d_in[3];
    const float* W       = (const float*)d_in[4];
    const float* bvec    = (const float*)d_in[5];
    const float* pW      = (const float*)d_in[6];
    const float* pb      = (const float*)d_in[7];
    float* out = (float*)d_out;

    cudaFuncSetAttribute(fused_kernel, cudaFuncAttributeMaxDynamicSharedMemorySize,
                         SMEM_TOTAL);
    cudaFuncSetAttribute(loss_kernel, cudaFuncAttributeMaxDynamicSharedMemorySize,
                         LOSS_SMEM);

    init_kernel<<<32, 256>>>();
    fused_kernel<<<NLSTM + NPROD, NT, SMEM_TOTAL>>>(q, we, W, bvec, lengths);
    loss_kernel<<<T_, 256, LOSS_SMEM>>>(a, lengths, pW, pb);
    final_kernel<<<1, 32>>>(lengths, out);
}

// round 17
// speedup vs baseline: 1.0584x; 1.0584x over previous
#include <cuda_runtime.h>
#include <math.h>
#include <stdint.h>

#define B_   32
#define T_   512
#define E_   256
#define H_   512
#define L_   50
#define NT   512
#define NLSTM 128    // recurrence blocks (bids 0..127 -> always first wave)
#define NLOSS 24     // loss consumer blocks on spare SMs
#define GPB  32      // blocks per batch-group (4 groups of 8 batches)

typedef unsigned long long ull;

// ---------------- device globals -----------------------------------------------
__device__ __align__(16) float g_hT[4 * 2 * H_ * 8];    // [grp][buf][hd][8b]
__device__ __align__(16) float g_Y[T_ * H_ * B_];       // [t][hd][32b] (zero-init .bss)
__device__ __align__(16) float g_Zx[(size_t)T_ * 2048 * B_]; // [t][col][32b]
__device__ float g_acc[B_];
__device__ unsigned g_barc[4 * 32];                     // group counters, 128B apart
__device__ unsigned g_t2;                               // loss work-steal counter

// ---------------- helpers --------------------------------------------------------
__device__ __forceinline__ ull ffma2_(ull a, ull b, ull c) {
    ull d;
    asm("fma.rn.f32x2 %0, %1, %2, %3;" : "=l"(d) : "l"(a), "l"(b), "l"(c));
    return d;
}
__device__ __forceinline__ ull splat2_(float x) {
    ull r; unsigned xi = __float_as_uint(x);
    asm("mov.b64 %0, {%1, %1};" : "=l"(r) : "r"(xi));
    return r;
}
__device__ __forceinline__ void cp16(uint32_t dst, const void* src) {
    asm volatile("cp.async.cg.shared.global [%0], [%1], 16;" :: "r"(dst), "l"(src));
}
__device__ __forceinline__ void cp_commit() { asm volatile("cp.async.commit_group;"); }
#define CP_WAIT(N) asm volatile("cp.async.wait_group %0;" :: "n"(N) : "memory")

__device__ __forceinline__ float fsig_(float x) {
    x = fminf(fmaxf(x, -30.f), 30.f);
    float e = __expf(-x);
    return __fdividef(1.f, 1.f + e);
}
__device__ __forceinline__ float ftanh_(float x) {
    x = fminf(fmaxf(x, -15.f), 15.f);
    float e = __expf(-2.f * x);
    return __fdividef(1.f - e, 1.f + e);
}

// ================================================================================
// Phase A: zx precompute.  grid = (T_ * 4); block 0 also resets state.
// ================================================================================
#define ZXD_OFF  0
#define ZWB_OFF  (256*32)
#define ZX_SMEM  ((8192 + 3*8192) * 4)
#define XT_PAD   261

__global__ void __launch_bounds__(256, 1)
zx_kernel(const int* __restrict__ q, const float* __restrict__ we,
          const float* __restrict__ W, const float* __restrict__ bvec,
          const int* __restrict__ lengths)
{
    extern __shared__ float sm[];
    float* XD = sm + ZXD_OFF;
    float* WB = sm + ZWB_OFF;
    float* XT = sm + ZWB_OFF;
    const uint32_t smu = (uint32_t)__cvta_generic_to_shared(sm);
    __shared__ int qrow[32];
    __shared__ int smax[1];

    const int tid = threadIdx.x;
    const int t   = blockIdx.x >> 2;
    const int c0  = (blockIdx.x & 3) << 9;

    if (blockIdx.x == 0) {                  // graph-replay-safe reset
        if (tid < 128) g_barc[tid] = 0u;
        if (tid < 32)  g_acc[tid] = 0.f;
        if (tid == 0)  g_t2 = 0u;
        float4 z4 = make_float4(0.f, 0.f, 0.f, 0.f);
        float4* hp4 = (float4*)g_hT;
        #pragma unroll
        for (int i = 0; i < 32; ++i) hp4[tid + (i << 8)] = z4;   // 32768 floats
    }

    if (tid < 32) {
        int v = lengths[tid];
        #pragma unroll
        for (int o = 16; o > 0; o >>= 1) v = max(v, __shfl_xor_sync(0xffffffffu, v, o));
        if (tid == 0) smax[0] = v;
        qrow[tid] = q[(tid << 9) + t];
    }
    __syncthreads();
    if (t >= smax[0]) return;               // never consumed (g_Y stays zero there)

    #pragma unroll
    for (int i = 0; i < 32; ++i) {
        int idx = tid + (i << 8);
        int b = idx >> 8, k = idx & 255;
        XT[b * XT_PAD + k] = we[(((size_t)qrow[b]) << 8) + k];
    }
    __syncthreads();
    float xbuf[32];
    #pragma unroll
    for (int i = 0; i < 32; ++i) {
        int idx = tid + (i << 8);
        int k = idx >> 5, b = idx & 31;
        xbuf[i] = XT[b * XT_PAD + k];
    }
    __syncthreads();
    #pragma unroll
    for (int i = 0; i < 32; ++i) {
        int idx = tid + (i << 8);
        int k = idx >> 5, b = idx & 31;
        XD[k * 32 + b] = xbuf[i];
    }
    __syncthreads();

    const int bq = tid & 3;
    const int cq = tid >> 2;

    #pragma unroll
    for (int pc = 0; pc < 2; ++pc) {
        #pragma unroll
        for (int i = 0; i < 8; ++i) {
            int u = tid + (i << 8);
            int kk = u >> 7, c16 = u & 127;
            cp16(smu + (uint32_t)((ZWB_OFF + pc * 8192 + kk * 512 + (c16 << 2)) * 4),
                 W + ((size_t)(pc * 16 + kk)) * 2048 + c0 + (c16 << 2));
        }
        cp_commit();
    }

    ull acc[4][8];
    #pragma unroll
    for (int i = 0; i < 4; ++i)
        #pragma unroll
        for (int j = 0; j < 8; ++j) acc[i][j] = 0ull;

    for (int kc = 0; kc < 16; ++kc) {
        if (kc < 15) { CP_WAIT(1); } else { CP_WAIT(0); }
        __syncthreads();
        const float* Wc = WB + (kc % 3) * 8192;
        const float* Xc = XD + kc * 16 * 32;
        #pragma unroll
        for (int kk = 0; kk < 16; ++kk) {
            ulonglong2 xa = *(const ulonglong2*)(Xc + kk * 32 + bq * 8);
            ulonglong2 xb = *(const ulonglong2*)(Xc + kk * 32 + bq * 8 + 4);
            float4 w0 = *(const float4*)(Wc + kk * 512 + cq * 8);
            float4 w1 = *(const float4*)(Wc + kk * 512 + cq * 8 + 4);
            ull ws[8];
            ws[0] = splat2_(w0.x); ws[1] = splat2_(w0.y);
            ws[2] = splat2_(w0.z); ws[3] = splat2_(w0.w);
            ws[4] = splat2_(w1.x); ws[5] = splat2_(w1.y);
            ws[6] = splat2_(w1.z); ws[7] = splat2_(w1.w);
            #pragma unroll
            for (int c = 0; c < 8; ++c) {
                acc[0][c] = ffma2_(xa.x, ws[c], acc[0][c]);
                acc[1][c] = ffma2_(xa.y, ws[c], acc[1][c]);
                acc[2][c] = ffma2_(xb.x, ws[c], acc[2][c]);
                acc[3][c] = ffma2_(xb.y, ws[c], acc[3][c]);
            }
        }
        if (kc + 2 < 16) {
            int buf = (kc + 2) % 3;
            #pragma unroll
            for (int i = 0; i < 8; ++i) {
                int u = tid + (i << 8);
                int kk = u >> 7, c16 = u & 127;
                cp16(smu + (uint32_t)((ZWB_OFF + buf * 8192 + kk * 512 + (c16 << 2)) * 4),
                     W + ((size_t)((kc + 2) * 16 + kk)) * 2048 + c0 + (c16 << 2));
            }
            cp_commit();
        }
    }

    #pragma unroll
    for (int c = 0; c < 8; ++c) {
        int cg = c0 + cq * 8 + c;
        float bb = __ldg(&bvec[cg]);
        float* outp = g_Zx + ((size_t)t * 2048 + cg) * 32 + bq * 8;
        #pragma unroll
        for (int bp = 0; bp < 4; ++bp) {
            union { ull u; float2 f; } v; v.u = acc[bp][c];
            v.f.x += bb; v.f.y += bb;
            *(float2*)(outp + bp * 2) = v.f;
        }
    }
}

// ================================================================================
// Phase B (fused): blocks 0..127 recurrence (round-14 body + barrier trim);
// blocks 128..151 loss consumers (work-steal t, gated on g_barc progress).
// ================================================================================
// lstm smem (floats):
#define WD_FLT   0                        // [512 k][64 c] = 32768
#define ZXS_FLT  32768                    // 2 x [64 c][8 b] = 1024
#define ZR_FLT   (ZXS_FLT + 1024)         // 33792 : [16 ws][64 c][8 b] = 8192
#define LEN_FLT  (ZR_FLT + 8192)          // 41984 : [8] ints
#define ZF_FLT   (LEN_FLT + 8)            // 41992 : [64 c][8 b] = 512  (end 42504)
// loss smem (floats):
#define LS_YS    0                        // [512][32] = 16384
#define LS_PW    16384                    // [512][50] = 25600
#define LS_LG    (16384 + 25600)          // 41984 : [50][32] = 1600
#define LS_MISC  (LS_LG + 1600)           // 43584 : misc ints
#define FUSED_FLOATS (LS_MISC + 16)       // 43600
#define FUSED_SMEM  (FUSED_FLOATS * 4)    // 174400 B

__global__ void __launch_bounds__(NT, 1)
fused_kernel(const int* __restrict__ a, const int* __restrict__ lengths,
             const float* __restrict__ W, const float* __restrict__ pW,
             const float* __restrict__ pb)
{
    extern __shared__ float sm[];
    const uint32_t smu = (uint32_t)__cvta_generic_to_shared(sm);
    const int tid = threadIdx.x;
    const int bid = blockIdx.x;

    if (bid >= NLSTM) {
        // ===================== loss consumer =====================
        if (tid >= 256) return;
        float* ys  = sm + LS_YS;
        float* pWs = sm + LS_PW;
        float* lg  = sm + LS_LG;
        int*   misc = (int*)(sm + LS_MISC);

        // per-group tmax (tid0 registers) + one-time pW load
        int tg0 = 0, tg1 = 0, tg2 = 0, tg3 = 0;
        if (tid == 0) {
            #pragma unroll
            for (int i = 0; i < 8; ++i) {
                tg0 = max(tg0, __ldg(&lengths[i]));
                tg1 = max(tg1, __ldg(&lengths[8 + i]));
                tg2 = max(tg2, __ldg(&lengths[16 + i]));
                tg3 = max(tg3, __ldg(&lengths[24 + i]));
            }
        }
        {
            const float4* ps = (const float4*)pW;
            float4* pd = (float4*)pWs;
            #pragma unroll
            for (int i = 0; i < 25; ++i) pd[tid + i * 256] = ps[tid + i * 256];
        }

        for (;;) {
            if (tid == 0) misc[0] = (int)atomicAdd(&g_t2, 1u);
            __syncthreads();
            const int t = misc[0];
            if (t >= T_) break;

            // gate: all groups with t < tmax_g must have finished step t
            if (tid == 0) {
                int tgs[4] = {tg0, tg1, tg2, tg3};
                #pragma unroll
                for (int g = 0; g < 4; ++g) {
                    if (t < tgs[g]) {
                        unsigned target = (unsigned)(t + 1) * GPB;
                        unsigned v;
                        do {
                            asm volatile("ld.acquire.gpu.global.u32 %0, [%1];"
                                         : "=r"(v) : "l"(&g_barc[g << 5]) : "memory");
                        } while (v < target);
                    }
                }
            }
            __syncthreads();

            // load y tile
            {
                const float4* src = (const float4*)(g_Y + (size_t)t * (H_ * B_));
                float4* dst = (float4*)ys;
                #pragma unroll
                for (int i = 0; i < 16; ++i) dst[tid + i * 256] = src[tid + i * 256];
            }
            __syncthreads();

            // logits (register-blocked FFMA2): thread = (bq = tid&3, l = tid>>2)
            {
                const int bq = tid & 3;
                const int l  = tid >> 2;
                if (l < 50) {
                    ull ac0 = 0ull, ac1 = 0ull, ac2 = 0ull, ac3 = 0ull;
                    #pragma unroll 4
                    for (int h = 0; h < 512; ++h) {
                        const ull* yp = (const ull*)(ys + (h << 5) + (bq << 3));
                        ull wv = splat2_(pWs[h * 50 + l]);
                        ac0 = ffma2_(yp[0], wv, ac0);
                        ac1 = ffma2_(yp[1], wv, ac1);
                        ac2 = ffma2_(yp[2], wv, ac2);
                        ac3 = ffma2_(yp[3], wv, ac3);
                    }
                    float bb = __ldg(&pb[l]);
                    union { ull u; float2 f; } v;
                    ull accs[4] = {ac0, ac1, ac2, ac3};
                    #pragma unroll
                    for (int j = 0; j < 4; ++j) {
                        v.u = accs[j];
                        lg[l * 32 + (bq << 3) + 2 * j]     = fmaxf(v.f.x + bb, 0.f);
                        lg[l * 32 + (bq << 3) + 2 * j + 1] = fmaxf(v.f.y + bb, 0.f);
                    }
                }
            }
            __syncthreads();

            if (tid < 32) {
                int b = tid;
                if (t < __ldg(&lengths[b])) {
                    float mx = lg[b];
                    #pragma unroll
                    for (int l = 1; l < 50; ++l) mx = fmaxf(mx, lg[l * 32 + b]);
                    float se = 0.f;
                    #pragma unroll
                    for (int l = 0; l < 50; ++l) se += expf(lg[l * 32 + b] - mx);
                    float lse = logf(se) + mx;
                    int lab = __ldg(&a[(b << 9) + t]);
                    atomicAdd(&g_acc[b], lse - lg[lab * 32 + b]);
                }
            }
            // loop-top __syncthreads orders xent reads before next lg writes
        }
        return;
    }

    // ===================== recurrence (round-14 body) =====================
    float* Wsm  = sm + WD_FLT;
    float* zxs  = sm + ZXS_FLT;
    float* zred = sm + ZR_FLT;
    int*   ls   = (int*)(sm + LEN_FLT);
    float* zfin = sm + ZF_FLT;

    const int grp = bid >> 5;              // 4 groups
    const int gb  = bid & 31;
    const int hd0 = gb << 4;               // 16 h-dims per block

    for (int i = tid; i < 512 * 64; i += NT) {
        int k = i >> 6, c = i & 63;        // c = gate*16 + jj
        Wsm[i] = W[((size_t)(256 + k)) * 2048 + (((c >> 4) << 9) + hd0 + (c & 15))];
    }
    if (tid < 8) ls[tid] = lengths[(grp << 3) + tid];
    __syncthreads();

    int tmax = ls[0];
    #pragma unroll
    for (int i = 1; i < 8; ++i) tmax = max(tmax, ls[i]);

    // zx(0) prefetch into buf 0
    if (tid < 128) {
        int r = tid >> 1, p = tid & 1;
        int gcol = ((r >> 4) << 9) + hd0 + (r & 15);
        cp16(smu + (uint32_t)((ZXS_FLT + (r << 3) + (p << 2)) * 4),
             g_Zx + (size_t)gcol * 32 + (grp << 3) + (p << 2));
    }
    cp_commit();

    const int wid  = tid >> 5, lane = tid & 31;
    const int bg   = lane & 1;
    const int cw   = lane >> 1;
    const int krow0 = wid << 5;

    const int gbb = tid & 7, gjj = (tid >> 3) & 15;
    const int mylen = ls[gbb];
    float c_st = 0.f, h_st = 0.f;
    const int rc = tid >> 3, rb = tid & 7;

    unsigned* barp = &g_barc[grp << 5];

    for (int t = 0; t < tmax; ++t) {
        // ---- issue zx(t+1) into the other buffer ----
        if (t + 1 < tmax && tid < 128) {
            int r = tid >> 1, p = tid & 1;
            int gcol = ((r >> 4) << 9) + hd0 + (r & 15);
            cp16(smu + (uint32_t)((ZXS_FLT + (((t + 1) & 1) << 9) + (r << 3) + (p << 2)) * 4),
                 g_Zx + ((size_t)((t + 1) << 11) + gcol) * 32 + (grp << 3) + (p << 2));
        }
        cp_commit();

        // ---- h-GEMM: 32 k-rows per warp, h LDG-direct from L2 (.cg) ----
        const float* hp = g_hT + (grp << 13) + ((t & 1) << 12)
                          + (krow0 << 3) + (bg << 2);
        const float* Wc = Wsm + (krow0 << 6) + (cw << 2);
        ull a0 = 0ull, a1 = 0ull, a2 = 0ull, a3 = 0ull;
        ull a4 = 0ull, a5 = 0ull, a6 = 0ull, a7 = 0ull;
        #pragma unroll 8
        for (int kk = 0; kk < 32; ++kk) {
            ull hx, hy;
            asm("ld.global.cg.v2.u64 {%0, %1}, [%2];"
                : "=l"(hx), "=l"(hy) : "l"(hp + (kk << 3)));
            float4 w = *(const float4*)(Wc + (kk << 6));
            ull w0 = splat2_(w.x), w1 = splat2_(w.y);
            ull w2 = splat2_(w.z), w3 = splat2_(w.w);
            a0 = ffma2_(hx, w0, a0);
            a1 = ffma2_(hy, w0, a1);
            a2 = ffma2_(hx, w1, a2);
            a3 = ffma2_(hy, w1, a3);
            a4 = ffma2_(hx, w2, a4);
            a5 = ffma2_(hy, w2, a5);
            a6 = ffma2_(hx, w3, a6);
            a7 = ffma2_(hy, w3, a7);
        }
        {
            ull* zru = (ull*)zred;
            int cb = (wid << 6) + (cw << 2);
            zru[((cb    ) << 2) + (bg << 1)]     = a0;
            zru[((cb    ) << 2) + (bg << 1) + 1] = a1;
            zru[((cb + 1) << 2) + (bg << 1)]     = a2;
            zru[((cb + 1) << 2) + (bg << 1) + 1] = a3;
            zru[((cb + 2) << 2) + (bg << 1)]     = a4;
            zru[((cb + 2) << 2) + (bg << 1) + 1] = a5;
            zru[((cb + 3) << 2) + (bg << 1)]     = a6;
            zru[((cb + 3) << 2) + (bg << 1) + 1] = a7;
        }
        CP_WAIT(1);
        __syncthreads();

        // ---- phase 1: 512-thread z reduction (incl. zx) ----
        {
            const float* zx_t = zxs + ((t & 1) << 9);
            float s0 = zx_t[(rc << 3) + rb], s1 = 0.f;
            #pragma unroll
            for (int ks = 0; ks < 16; ks += 2) {
                s0 += zred[(((ks << 6) + rc) << 3) + rb];
                s1 += zred[((((ks + 1) << 6) + rc) << 3) + rb];
            }
            zfin[(rc << 3) + rb] = s0 + s1;
        }
        __syncthreads();

        // ---- phase 2: gates + state update, then gate-warp barrier + arrive ----
        if (tid < 128) {
            float gt[4];
            #pragma unroll
            for (int gate = 0; gate < 4; ++gate)
                gt[gate] = zfin[(((gate << 4) + gjj) << 3) + gbb];
            float i_ = fsig_(gt[0]);
            float jt = ftanh_(gt[1]);
            float f_ = fsig_(gt[2] + 1.f);
            float o_ = fsig_(gt[3]);
            float cnew = c_st * f_ + i_ * jt;
            float hnew = ftanh_(cnew) * o_;
            bool m = t < mylen;
            c_st = m ? cnew : c_st;
            float hout = m ? hnew : h_st;
            h_st = hout;
            int hd = hd0 + gjj;
            g_hT[(grp << 13) + (((t + 1) & 1) << 12) + (hd << 3) + gbb] = hout;
            g_Y[((size_t)(t << 9) + hd) * 32 + (grp << 3) + gbb] = m ? hnew : 0.f;
            asm volatile("bar.sync 1, 128;" ::: "memory");   // gate stores done
            if (tid == 0) {
                asm volatile("red.release.gpu.global.add.u32 [%0], %1;"
                             :: "l"(barp), "r"(1u) : "memory");
                unsigned target = (unsigned)(t + 1) * GPB;
                unsigned v;
                do {
                    asm volatile("ld.acquire.gpu.global.u32 %0, [%1];"
                                 : "=r"(v) : "l"(barp) : "memory");
                } while (v < target);
            }
        }
        __syncthreads();
    }
}

// ================================================================================
// final scalar
// ================================================================================
__global__ void final_kernel(const int* __restrict__ lengths, float* __restrict__ out) {
    if (threadIdx.x == 0) {
        float s = 0.f;
        for (int b = 0; b < B_; ++b) s += g_acc[b] / (float)lengths[b];
        out[0] = s * (1.f / (float)B_);
    }
}

// ---------------- launch ----------------------------------------------------------
extern "C" void kernel_launch(void* const* d_in, const int* in_sizes, int n_in,
                              void* d_out, int out_size) {
    const int*   q       = (const int*)d_in[0];
    const int*   a       = (const int*)d_in[1];
    const int*   lengths = (const int*)d_in[2];
    const float* we      = (const float*)d_in[3];
    const float* W       = (const float*)d_in[4];
    const float* bvec    = (const float*)d_in[5];
    const float* pW      = (const float*)d_in[6];
    const float* pb      = (const float*)d_in[7];
    float* out = (float*)d_out;

    cudaFuncSetAttribute(zx_kernel, cudaFuncAttributeMaxDynamicSharedMemorySize,
                         ZX_SMEM);
    cudaFuncSetAttribute(fused_kernel, cudaFuncAttributeMaxDynamicSharedMemorySize,
                         FUSED_SMEM);

    zx_kernel<<<T_ * 4, 256, ZX_SMEM>>>(q, we, W, bvec, lengths);
    fused_kernel<<<NLSTM + NLOSS, NT, FUSED_SMEM>>>(a, lengths, W, pW, pb);
    final_kernel<<<1, 32>>>(lengths, out);
}